// round 1
// baseline (speedup 1.0000x reference)
#include <cuda_runtime.h>
#include <math.h>

#define A_N 8192
#define K_N 64
#define D_N 128
#define B_N 16384

// Scratch: per-anchor npair losses [0, A_N) and per-row norms [A_N, A_N+B_N).
__device__ float g_part[A_N + B_N];
// 1 if index buffers are int64, 0 if int32. Recomputed every launch (deterministic).
__device__ int g_is64;

// ---------------------------------------------------------------------------
// Detect index dtype: all indices are in [0, 16384), so if the buffer is
// int64 (little-endian), every odd 32-bit word is zero. If int32, odd words
// are random indices (prob all-zero ~ 0). Scan the first A_N*K_N words of
// neg_ind (present under either dtype). Single block -> no races.
// ---------------------------------------------------------------------------
__global__ void detect_kernel(const unsigned int* __restrict__ neg, int nwords) {
    unsigned int acc = 0;
    for (int i = 2 * threadIdx.x + 1; i < nwords; i += 2 * blockDim.x)
        acc |= neg[i];
    #pragma unroll
    for (int o = 16; o; o >>= 1) acc |= __shfl_xor_sync(0xffffffffu, acc, o);
    __shared__ unsigned int s[32];
    int w = threadIdx.x >> 5, l = threadIdx.x & 31;
    if (l == 0) s[w] = acc;
    __syncthreads();
    if (threadIdx.x == 0) {
        unsigned int r = 0;
        int nw = blockDim.x >> 5;
        for (int i = 0; i < nw; i++) r |= s[i];
        g_is64 = (r == 0u) ? 1 : 0;
    }
}

__device__ __forceinline__ int load_idx(const void* p, long long i, int is64) {
    return is64 ? (int)((const long long*)p)[i] : ((const int*)p)[i];
}

// ---------------------------------------------------------------------------
// N-pair loss: one block (128 threads = 4 warps) per anchor.
//   inner[k] = a . n_k - a . p     (a.p computed once)
//   per_anchor = logaddexp(0, logsumexp_k(inner))
// ---------------------------------------------------------------------------
__global__ __launch_bounds__(128) void npair_kernel(
    const float* __restrict__ E,
    const void* __restrict__ anc,
    const void* __restrict__ pos,
    const void* __restrict__ neg)
{
    __shared__ float4 sA4[D_N / 4];   // anchor row
    __shared__ float  sInner[K_N];
    __shared__ float  sRed[4];

    const int a  = blockIdx.x;
    const int t  = threadIdx.x;
    const int w  = t >> 5;
    const int l  = t & 31;
    const int is64 = g_is64;

    const int ai = load_idx(anc, a, is64);
    const int pi = load_idx(pos, a, is64);

    // Load anchor & positive element (one float per thread), cache anchor in smem.
    const float av = E[(long long)ai * D_N + t];
    const float pv = E[(long long)pi * D_N + t];
    ((float*)sA4)[t] = av;

    // Block-reduce a.p
    float ap = av * pv;
    #pragma unroll
    for (int o = 16; o; o >>= 1) ap += __shfl_xor_sync(0xffffffffu, ap, o);
    if (l == 0) sRed[w] = ap;
    __syncthreads();
    const float apf = sRed[0] + sRed[1] + sRed[2] + sRed[3];

    const float4 a4 = sA4[l];

    // Each warp handles 16 negatives. Lane l reads float4 -> 512B coalesced/warp.
    const long long kbase = (long long)a * K_N + (long long)w * 16;
    #pragma unroll 4
    for (int j = 0; j < 16; j++) {
        const int k = w * 16 + j;
        const long long nidx = (long long)load_idx(neg, kbase + j, is64);
        const float4* __restrict__ row = (const float4*)(E + nidx * D_N);
        const float4 v = __ldg(row + l);
        float d = v.x * a4.x + v.y * a4.y + v.z * a4.z + v.w * a4.w;
        #pragma unroll
        for (int o = 16; o; o >>= 1) d += __shfl_xor_sync(0xffffffffu, d, o);
        if (l == 0) sInner[k] = d - apf;
    }
    __syncthreads();

    // Warp 0: stable logsumexp over 64 values, then logaddexp(0, lse).
    if (w == 0) {
        const float v0 = sInner[l];
        const float v1 = sInner[l + 32];
        float m = fmaxf(v0, v1);
        #pragma unroll
        for (int o = 16; o; o >>= 1) m = fmaxf(m, __shfl_xor_sync(0xffffffffu, m, o));
        float s = expf(v0 - m) + expf(v1 - m);
        #pragma unroll
        for (int o = 16; o; o >>= 1) s += __shfl_xor_sync(0xffffffffu, s, o);
        if (l == 0) {
            const float lse = m + logf(s);
            // logaddexp(0, lse), stable both directions
            const float pa = fmaxf(lse, 0.0f) + log1pf(expf(-fabsf(lse)));
            g_part[a] = pa;
        }
    }
}

// ---------------------------------------------------------------------------
// Per-row L2 norms: one warp per row (4 rows per 128-thread block).
// ---------------------------------------------------------------------------
__global__ __launch_bounds__(128) void norm_kernel(const float* __restrict__ E) {
    const int row = blockIdx.x * 4 + (threadIdx.x >> 5);
    const int l   = threadIdx.x & 31;
    const float4* __restrict__ r = (const float4*)(E + (long long)row * D_N);
    const float4 v = r[l];
    float s = v.x * v.x + v.y * v.y + v.z * v.z + v.w * v.w;
    #pragma unroll
    for (int o = 16; o; o >>= 1) s += __shfl_xor_sync(0xffffffffu, s, o);
    if (l == 0) g_part[A_N + row] = sqrtf(s);
}

// ---------------------------------------------------------------------------
// Deterministic final reduction (single block, fixed iteration order).
// out = mean(per_anchor) + 0.25 * mean(norms)
// ---------------------------------------------------------------------------
__global__ void final_kernel(float* __restrict__ out) {
    __shared__ float s[32];
    const float invA = 1.0f / (float)A_N;
    const float cB   = 0.25f / (float)B_N;
    float acc = 0.0f;
    for (int i = threadIdx.x; i < A_N + B_N; i += blockDim.x) {
        const float v = g_part[i];
        acc += (i < A_N) ? v * invA : v * cB;
    }
    #pragma unroll
    for (int o = 16; o; o >>= 1) acc += __shfl_xor_sync(0xffffffffu, acc, o);
    const int w = threadIdx.x >> 5, l = threadIdx.x & 31;
    if (l == 0) s[w] = acc;
    __syncthreads();
    if (threadIdx.x == 0) {
        float r = 0.0f;
        const int nw = (int)(blockDim.x >> 5);
        for (int i = 0; i < nw; i++) r += s[i];
        out[0] = r;
    }
}

extern "C" void kernel_launch(void* const* d_in, const int* in_sizes, int n_in,
                              void* d_out, int out_size) {
    const float* E   = (const float*)d_in[0];   // image_embed [B, D] f32
    const void*  anc = d_in[1];                 // anc_ind [A]  int32/int64
    const void*  pos = d_in[2];                 // pos_ind [A]
    const void*  neg = d_in[3];                 // neg_ind [A, K]
    float* out = (float*)d_out;

    detect_kernel<<<1, 1024>>>((const unsigned int*)neg, A_N * K_N);
    npair_kernel<<<A_N, 128>>>(E, anc, pos, neg);
    norm_kernel<<<B_N / 4, 128>>>(E);
    final_kernel<<<1, 1024>>>(out);
}

// round 3
// speedup vs baseline: 2.5996x; 2.5996x over previous
#include <cuda_runtime.h>
#include <math.h>

#define A_N 8192
#define K_N 64
#define D_N 128
#define B_N 16384

// Scratch: per-anchor npair losses [0, A_N) and per-row norms [A_N, A_N+B_N).
__device__ float g_part[A_N + B_N];
// 1 if index buffers are int64, 0 if int32. Recomputed every launch (deterministic).
__device__ int g_is64;

// ---------------------------------------------------------------------------
// Detect index dtype. Indices < 16384, so for int64 (LE) every odd 32-bit word
// is zero; for int32 the odd words are random indices (P(word==0) ~= 6e-5 per
// word, 4096 samples -> all-zero probability ~0). Tiny scan: 8192 words = 32KB.
// ---------------------------------------------------------------------------
__global__ void detect_kernel(const unsigned int* __restrict__ neg) {
    unsigned int acc = 0;
    for (int i = 2 * threadIdx.x + 1; i < 8192; i += 2 * blockDim.x)
        acc |= neg[i];
    #pragma unroll
    for (int o = 16; o; o >>= 1) acc |= __shfl_xor_sync(0xffffffffu, acc, o);
    __shared__ unsigned int s[4];
    int w = threadIdx.x >> 5, l = threadIdx.x & 31;
    if (l == 0) s[w] = acc;
    __syncthreads();
    if (threadIdx.x == 0)
        g_is64 = ((s[0] | s[1] | s[2] | s[3]) == 0u) ? 1 : 0;
}

__device__ __forceinline__ int load_idx(const void* p, long long i, int is64) {
    return is64 ? (int)((const long long*)p)[i] : ((const int*)p)[i];
}

// Merge two multi-dot partial registers at lane-distance s:
// lanes with (lane & s)==0 end holding x's dot reduced over {l, l^s};
// lanes with (lane & s)!=0 end holding y's dot reduced over {l, l^s}.
// Cost: 1 shuffle + 2 selects (vs 2 full butterflies).
__device__ __forceinline__ float merge2(float x, float y, int s, int lane) {
    float send = (lane & s) ? x : y;
    float keep = (lane & s) ? y : x;
    float t = __shfl_xor_sync(0xffffffffu, send, s);
    return keep + t;
}

// ---------------------------------------------------------------------------
// Fused kernel:
//   blocks [0, A_N): one block (4 warps) per anchor, N-pair loss.
//   blocks [A_N, A_N + B_N/4): per-row L2 norms, 4 rows per block.
// ---------------------------------------------------------------------------
__global__ __launch_bounds__(128) void fused_kernel(
    const float* __restrict__ E,
    const void* __restrict__ anc,
    const void* __restrict__ pos,
    const void* __restrict__ neg)
{
    const int t = threadIdx.x;
    const int w = t >> 5;
    const int l = t & 31;

    if (blockIdx.x >= A_N) {
        // ---- L2 norms: one warp per row ----
        const int row = (blockIdx.x - A_N) * 4 + w;
        const float4 v = ((const float4*)(E + (long long)row * D_N))[l];
        float s = v.x * v.x + v.y * v.y + v.z * v.z + v.w * v.w;
        #pragma unroll
        for (int o = 16; o; o >>= 1) s += __shfl_xor_sync(0xffffffffu, s, o);
        if (l == 0) g_part[A_N + row] = sqrtf(s);
        return;
    }

    __shared__ float sA[D_N];
    __shared__ float sRed[4];
    __shared__ float sM[4], sS[4];

    const int a = blockIdx.x;
    const int is64 = g_is64;

    const int ai = load_idx(anc, a, is64);
    const int pi = load_idx(pos, a, is64);

    const float av = E[(long long)ai * D_N + t];
    const float pv = E[(long long)pi * D_N + t];
    sA[t] = av;

    // Block-reduce a.p (computed once, subtracted as a scalar)
    float ap = av * pv;
    #pragma unroll
    for (int o = 16; o; o >>= 1) ap += __shfl_xor_sync(0xffffffffu, ap, o);
    if (l == 0) sRed[w] = ap;
    __syncthreads();
    const float apf = sRed[0] + sRed[1] + sRed[2] + sRed[3];

    const float4 a4 = ((const float4*)sA)[l];

    // ---- 16 negatives per warp; coalesced float4 gathers, front-batched ----
    const long long kbase = (long long)a * K_N + (long long)w * 16;
    float d[16];
    #pragma unroll
    for (int j = 0; j < 16; j++) {
        const long long nidx = (long long)load_idx(neg, kbase + j, is64);
        const float4 v = __ldg((const float4*)(E + nidx * D_N) + l);
        d[j] = v.x * a4.x + v.y * a4.y + v.z * a4.z + v.w * a4.w;
    }

    // ---- merge-tree reduce: 16 dots x 32 lanes in 16 shuffles ----
    float e[8], f[4], g[2], h;
    #pragma unroll
    for (int m = 0; m < 8; m++) e[m] = merge2(d[2 * m], d[2 * m + 1], 16, l);
    #pragma unroll
    for (int m = 0; m < 4; m++) f[m] = merge2(e[2 * m], e[2 * m + 1], 8, l);
    #pragma unroll
    for (int m = 0; m < 2; m++) g[m] = merge2(f[2 * m], f[2 * m + 1], 4, l);
    h = merge2(g[0], g[1], 2, l);
    h += __shfl_xor_sync(0xffffffffu, h, 1);
    // lane l holds dot k(l); each dot duplicated on a lane pair (bit 0).
    const float inner = h - apf;

    // ---- in-warp logsumexp over this warp's 16 dots (values duplicated x2) ----
    float m1 = inner;
    #pragma unroll
    for (int o = 16; o; o >>= 1) m1 = fmaxf(m1, __shfl_xor_sync(0xffffffffu, m1, o));
    float s1 = __expf(inner - m1);
    #pragma unroll
    for (int o = 16; o; o >>= 1) s1 += __shfl_xor_sync(0xffffffffu, s1, o);
    if (l == 0) { sM[w] = m1; sS[w] = 0.5f * s1; }  // halve: duplicates
    __syncthreads();

    if (t == 0) {
        float M = fmaxf(fmaxf(sM[0], sM[1]), fmaxf(sM[2], sM[3]));
        float S = sS[0] * __expf(sM[0] - M) + sS[1] * __expf(sM[1] - M)
                + sS[2] * __expf(sM[2] - M) + sS[3] * __expf(sM[3] - M);
        const float lse = M + logf(S);
        const float pa = fmaxf(lse, 0.0f) + log1pf(expf(-fabsf(lse)));
        g_part[a] = pa;
    }
}

// ---------------------------------------------------------------------------
// Deterministic final reduction (single block, fixed order, float4 loads).
// out = mean(per_anchor) + 0.25 * mean(norms)
// ---------------------------------------------------------------------------
__global__ void final_kernel(float* __restrict__ out) {
    __shared__ float s[32];
    const float invA = 1.0f / (float)A_N;
    const float cB   = 0.25f / (float)B_N;
    const float4* __restrict__ p4 = (const float4*)g_part;
    float accA = 0.0f, accB = 0.0f;
    for (int i = threadIdx.x; i < A_N / 4; i += blockDim.x) {
        const float4 v = p4[i];
        accA += (v.x + v.y) + (v.z + v.w);
    }
    for (int i = A_N / 4 + threadIdx.x; i < (A_N + B_N) / 4; i += blockDim.x) {
        const float4 v = p4[i];
        accB += (v.x + v.y) + (v.z + v.w);
    }
    float acc = accA * invA + accB * cB;
    #pragma unroll
    for (int o = 16; o; o >>= 1) acc += __shfl_xor_sync(0xffffffffu, acc, o);
    const int w = threadIdx.x >> 5, l = threadIdx.x & 31;
    if (l == 0) s[w] = acc;
    __syncthreads();
    if (threadIdx.x == 0) {
        float r = 0.0f;
        const int nw = (int)(blockDim.x >> 5);
        for (int i = 0; i < nw; i++) r += s[i];
        out[0] = r;
    }
}

extern "C" void kernel_launch(void* const* d_in, const int* in_sizes, int n_in,
                              void* d_out, int out_size) {
    const float* E   = (const float*)d_in[0];   // image_embed [B, D] f32
    const void*  anc = d_in[1];                 // anc_ind [A]
    const void*  pos = d_in[2];                 // pos_ind [A]
    const void*  neg = d_in[3];                 // neg_ind [A, K]
    float* out = (float*)d_out;

    detect_kernel<<<1, 128>>>((const unsigned int*)neg);
    fused_kernel<<<A_N + B_N / 4, 128>>>(E, anc, pos, neg);
    final_kernel<<<1, 1024>>>(out);
}